// round 1
// baseline (speedup 1.0000x reference)
#include <cuda_runtime.h>
#include <math.h>

// ---- model constants ----
#define B_SZ    16384
#define N_BAS   32
#define T_STEPS 300
#define HIDN    64
#define M_TOT   (B_SZ * 2)          // 32768 channels
#define DT_F    (1.0f / 300.0f)

// coef[t][n] = x_{t+1} * psi_{t+1}[n] / sum(psi_{t+1})   (batch-independent)
__device__ float g_coef[T_STEPS * N_BAS];

__global__ void coef_kernel(const float* __restrict__ c,
                            const float* __restrict__ s2) {
    int t = blockIdx.x * blockDim.x + threadIdx.x;
    if (t >= T_STEPS) return;
    float x = powf(1.0f - DT_F, (float)(t + 1));
    float psi[N_BAS];
    float sum = 0.0f;
#pragma unroll
    for (int n = 0; n < N_BAS; n++) {
        float dx = x - c[n];
        float p = expf(-0.5f * dx * dx / s2[n]);
        psi[n] = p;
        sum += p;
    }
    float inv = x / sum;
#pragma unroll
    for (int n = 0; n < N_BAS; n++) g_coef[t * N_BAS + n] = psi[n] * inv;
}

// One thread = one channel m (b = m>>1, d = m&1). 128 threads/block.
__global__ __launch_bounds__(128)
void ndp_kernel(const float* __restrict__ state,
                const float* __restrict__ fc1_w, const float* __restrict__ fc1_b,
                const float* __restrict__ fc2m_w, const float* __restrict__ fc2m_b,
                const float* __restrict__ sig_w, const float* __restrict__ sig_b,
                const float* __restrict__ val_w, const float* __restrict__ val_b,
                float* __restrict__ outA,   // [M, 300]
                float* __restrict__ outS,   // [M]
                float* __restrict__ outV)   // [M, 300]
{
    __shared__ float sW1[HIDN * 3];
    __shared__ float sB1[HIDN];
    __shared__ float sW2[66 * HIDN];
    __shared__ float sB2[66];
    __shared__ float sSW[2 * HIDN];
    __shared__ float sVW[2 * HIDN];
    __shared__ float sSB[2];
    __shared__ float sVB[2];
    __shared__ float tile[4][32 * 31];   // per-warp transpose tile, pitch 31 (odd)

    const int tid = threadIdx.x;

    for (int i = tid; i < HIDN * 3; i += 128) sW1[i] = fc1_w[i];
    for (int i = tid; i < HIDN; i += 128)     sB1[i] = fc1_b[i];
    for (int i = tid; i < 66 * HIDN; i += 128) sW2[i] = fc2m_w[i];
    for (int i = tid; i < 66; i += 128)       sB2[i] = fc2m_b[i];
    for (int i = tid; i < 2 * HIDN; i += 128) { sSW[i] = sig_w[i]; sVW[i] = val_w[i]; }
    if (tid < 2) { sSB[tid] = sig_b[tid]; sVB[tid] = val_b[tid]; }
    __syncthreads();

    const int m = blockIdx.x * 128 + tid;   // grid exactly covers M_TOT
    const int b = m >> 1;
    const int d = m & 1;

    const float s0 = state[b * 3 + 0];
    const float s1 = state[b * 3 + 1];
    const float s2v = state[b * 3 + 2];

    // ---- MLP hidden layer: h = tanh(state @ W1^T + b1) * 0.1 ----
    float h[HIDN];
#pragma unroll
    for (int j = 0; j < HIDN; j++) {
        float a = fmaf(s0, sW1[j * 3 + 0],
                  fmaf(s1, sW1[j * 3 + 1],
                  fmaf(s2v, sW1[j * 3 + 2], sB1[j])));
        h[j] = tanhf(a) * 0.1f;
    }

    // 64-wide dot against a shared-memory row (fully unrolled, 4 partial accums)
    auto dot64 = [&](const float* __restrict__ row) -> float {
        float a0 = 0.f, a1 = 0.f, a2 = 0.f, a3 = 0.f;
#pragma unroll
        for (int j = 0; j < HIDN; j += 4) {
            a0 = fmaf(h[j + 0], row[j + 0], a0);
            a1 = fmaf(h[j + 1], row[j + 1], a1);
            a2 = fmaf(h[j + 2], row[j + 2], a2);
            a3 = fmaf(h[j + 3], row[j + 3], a3);
        }
        return (a0 + a1) + (a2 + a3);
    };

    const float goal = dot64(&sW2[d * HIDN]) + sB2[d];

    float w[N_BAS];
#pragma unroll
    for (int n = 0; n < N_BAS; n++)
        w[n] = dot64(&sW2[(2 + d * N_BAS + n) * HIDN]) + sB2[2 + d * N_BAS + n];

    float az = dot64(&sW2[65 * HIDN]) + sB2[65];
    az = fminf(fmaxf(az, 0.5f), 30.0f);

    const float sgv = 1.0f / (1.0f + expf(-(dot64(&sSW[d * HIDN]) + sSB[d]))) + 0.001f;
    const float vv  = dot64(&sVW[d * HIDN]) + sVB[d];

    outS[m] = sgv;

    // ---- DMP Euler rollout ----
    const float y0 = d ? s1 : s0;
    float y = y0;
    float z = 0.01f;                 // z0 = dy0 * tau
    const float G  = goal - y0;
    const float bz = az * 0.25f;

    const int lane = tid & 31;
    const int warp = tid >> 5;
    float* wt = tile[warp];
    const int m0 = m - lane;

    for (int ch = 0; ch < 10; ch++) {        // 10 chunks of 30 steps
#pragma unroll 6
        for (int s = 0; s < 30; s++) {
            const int t = ch * 30 + s;
            const float4* cf = (const float4*)&g_coef[t * N_BAS];
            float d0 = 0.f, d1 = 0.f, d2 = 0.f, d3 = 0.f;
#pragma unroll
            for (int i = 0; i < 8; i += 4) {
                float4 f0 = __ldg(cf + i + 0);
                float4 f1 = __ldg(cf + i + 1);
                float4 f2 = __ldg(cf + i + 2);
                float4 f3 = __ldg(cf + i + 3);
                d0 = fmaf(w[4 * i + 0],  f0.x, d0);
                d1 = fmaf(w[4 * i + 1],  f0.y, d1);
                d2 = fmaf(w[4 * i + 2],  f0.z, d2);
                d3 = fmaf(w[4 * i + 3],  f0.w, d3);
                d0 = fmaf(w[4 * i + 4],  f1.x, d0);
                d1 = fmaf(w[4 * i + 5],  f1.y, d1);
                d2 = fmaf(w[4 * i + 6],  f1.z, d2);
                d3 = fmaf(w[4 * i + 7],  f1.w, d3);
                d0 = fmaf(w[4 * i + 8],  f2.x, d0);
                d1 = fmaf(w[4 * i + 9],  f2.y, d1);
                d2 = fmaf(w[4 * i + 10], f2.z, d2);
                d3 = fmaf(w[4 * i + 11], f2.w, d3);
                d0 = fmaf(w[4 * i + 12], f3.x, d0);
                d1 = fmaf(w[4 * i + 13], f3.y, d1);
                d2 = fmaf(w[4 * i + 14], f3.z, d2);
                d3 = fmaf(w[4 * i + 15], f3.w, d3);
            }
            const float dot = (d0 + d1) + (d2 + d3);

            wt[lane * 31 + s] = z * DT_F;    // a[t] = Y[t+1]-Y[t] = z_t * DT
            const float dz = fmaf(az, fmaf(bz, goal - y, -z), G * dot);
            y = fmaf(z, DT_F, y);
            z = fmaf(dz, DT_F, z);
        }
        __syncwarp();
        // transposed coalesced writeback: one 120B row per channel
#pragma unroll
        for (int r = 0; r < 32; r++) {
            if (lane < 30)
                outA[(size_t)(m0 + r) * 300 + ch * 30 + lane] = wt[r * 31 + lane];
        }
        __syncwarp();
    }

    // ---- value: broadcast over T, coalesced via shuffle ----
#pragma unroll 1
    for (int r = 0; r < 32; r++) {
        const float vr = __shfl_sync(0xffffffffu, vv, r);
        float* base = outV + (size_t)(m0 + r) * 300;
        for (int t = lane; t < 300; t += 32) base[t] = vr;
    }
}

extern "C" void kernel_launch(void* const* d_in, const int* in_sizes, int n_in,
                              void* d_out, int out_size) {
    const float* state  = (const float*)d_in[0];
    const float* fc1_w  = (const float*)d_in[1];
    const float* fc1_b  = (const float*)d_in[2];
    const float* fc2m_w = (const float*)d_in[3];
    const float* fc2m_b = (const float*)d_in[4];
    const float* sig_w  = (const float*)d_in[5];
    const float* sig_b  = (const float*)d_in[6];
    const float* val_w  = (const float*)d_in[7];
    const float* val_b  = (const float*)d_in[8];
    const float* dmp_c  = (const float*)d_in[9];
    const float* dmp_s2 = (const float*)d_in[10];

    float* out = (float*)d_out;
    float* outA = out;                                   // [B,2,300]
    float* outS = out + (size_t)M_TOT * T_STEPS;         // [B,2,1]
    float* outV = outS + M_TOT;                          // [B,2,300]

    coef_kernel<<<1, 320>>>(dmp_c, dmp_s2);
    ndp_kernel<<<M_TOT / 128, 128>>>(state, fc1_w, fc1_b, fc2m_w, fc2m_b,
                                     sig_w, sig_b, val_w, val_b,
                                     outA, outS, outV);
}

// round 2
// speedup vs baseline: 1.1343x; 1.1343x over previous
#include <cuda_runtime.h>
#include <math.h>

// ---- model constants ----
#define B_SZ    16384
#define N_BAS   32
#define T_STEPS 300
#define HIDN    64
#define M_TOT   (B_SZ * 2)          // 32768 channels
#define DT_F    (1.0f / 300.0f)

// scratch (static device globals — allocation-free)
__device__ float  g_coef[T_STEPS * N_BAS];   // [t][n]  coef = x*psi/sum(psi)
__device__ float  g_wT[N_BAS * M_TOT];       // [n][m]  G-prescaled basis weights
__device__ float4 g_par[M_TOT];              // goal, az, y0, value
__device__ float  g_F[T_STEPS * M_TOT];      // [t][m]  forcing term G*(w·coef)

// ---------------------------------------------------------------------------
// coef[t][n] = x_{t+1} * psi_{t+1}[n] / sum(psi_{t+1})   (batch-independent)
__global__ void coef_kernel(const float* __restrict__ c,
                            const float* __restrict__ s2) {
    int t = blockIdx.x * blockDim.x + threadIdx.x;
    if (t >= T_STEPS) return;
    float x = powf(1.0f - DT_F, (float)(t + 1));
    float psi[N_BAS];
    float sum = 0.0f;
#pragma unroll
    for (int n = 0; n < N_BAS; n++) {
        float dx = x - c[n];
        float p = expf(-0.5f * dx * dx / s2[n]);
        psi[n] = p;
        sum += p;
    }
    float inv = x / sum;
#pragma unroll
    for (int n = 0; n < N_BAS; n++) g_coef[t * N_BAS + n] = psi[n] * inv;
}

// ---------------------------------------------------------------------------
// params: MLP head per channel. One thread = one channel m.
__global__ __launch_bounds__(128)
void params_kernel(const float* __restrict__ state,
                   const float* __restrict__ fc1_w, const float* __restrict__ fc1_b,
                   const float* __restrict__ fc2m_w, const float* __restrict__ fc2m_b,
                   const float* __restrict__ sig_w, const float* __restrict__ sig_b,
                   const float* __restrict__ val_w, const float* __restrict__ val_b,
                   float* __restrict__ outS) {
    __shared__ float sW1[HIDN * 3];
    __shared__ float sB1[HIDN];
    __shared__ float sW2[66 * HIDN];
    __shared__ float sB2[66];
    __shared__ float sSW[2 * HIDN];
    __shared__ float sVW[2 * HIDN];
    __shared__ float sSB[2];
    __shared__ float sVB[2];

    const int tid = threadIdx.x;
    for (int i = tid; i < HIDN * 3; i += 128)  sW1[i] = fc1_w[i];
    for (int i = tid; i < HIDN; i += 128)      sB1[i] = fc1_b[i];
    for (int i = tid; i < 66 * HIDN; i += 128) sW2[i] = fc2m_w[i];
    for (int i = tid; i < 66; i += 128)        sB2[i] = fc2m_b[i];
    for (int i = tid; i < 2 * HIDN; i += 128) { sSW[i] = sig_w[i]; sVW[i] = val_w[i]; }
    if (tid < 2) { sSB[tid] = sig_b[tid]; sVB[tid] = val_b[tid]; }
    __syncthreads();

    const int m = blockIdx.x * 128 + tid;
    const int b = m >> 1;
    const int d = m & 1;

    const float s0 = state[b * 3 + 0];
    const float s1 = state[b * 3 + 1];
    const float s2v = state[b * 3 + 2];

    float h[HIDN];
#pragma unroll
    for (int j = 0; j < HIDN; j++) {
        float a = fmaf(s0, sW1[j * 3 + 0],
                  fmaf(s1, sW1[j * 3 + 1],
                  fmaf(s2v, sW1[j * 3 + 2], sB1[j])));
        h[j] = tanhf(a) * 0.1f;
    }

    auto dot64 = [&](const float* __restrict__ row) -> float {
        float a0 = 0.f, a1 = 0.f, a2 = 0.f, a3 = 0.f;
#pragma unroll
        for (int j = 0; j < HIDN; j += 4) {
            a0 = fmaf(h[j + 0], row[j + 0], a0);
            a1 = fmaf(h[j + 1], row[j + 1], a1);
            a2 = fmaf(h[j + 2], row[j + 2], a2);
            a3 = fmaf(h[j + 3], row[j + 3], a3);
        }
        return (a0 + a1) + (a2 + a3);
    };

    const float goal = dot64(&sW2[d * HIDN]) + sB2[d];
    const float y0 = d ? s1 : s0;
    const float G = goal - y0;

    // az from row 65 (overlaps w[d=1][31] per reference slicing)
    float az = dot64(&sW2[65 * HIDN]) + sB2[65];
    az = fminf(fmaxf(az, 0.5f), 30.0f);

    // G-prescaled weights, stored transposed [n][M] for coalesced GEMM reads
#pragma unroll
    for (int n = 0; n < N_BAS; n++) {
        float wn = dot64(&sW2[(2 + d * N_BAS + n) * HIDN]) + sB2[2 + d * N_BAS + n];
        g_wT[n * M_TOT + m] = wn * G;
    }

    const float sgv = 1.0f / (1.0f + expf(-(dot64(&sSW[d * HIDN]) + sSB[d]))) + 0.001f;
    const float vv  = dot64(&sVW[d * HIDN]) + sVB[d];

    outS[m] = sgv;
    g_par[m] = make_float4(goal, az, y0, vv);
}

// ---------------------------------------------------------------------------
// GEMM: F[t][m] = sum_n wT[n][m] * coef[t][n]   (G already folded into wT)
// grid (M/128, T/30): high occupancy since t-chunks are parallel.
__global__ __launch_bounds__(128)
void gemm_kernel() {
    __shared__ float sc[30 * N_BAS];

    const int tid = threadIdx.x;
    const int m = blockIdx.x * 128 + tid;
    const int t0 = blockIdx.y * 30;

    for (int i = tid; i < 30 * N_BAS; i += 128) sc[i] = g_coef[t0 * N_BAS + i];
    __syncthreads();

    float w[N_BAS];
#pragma unroll
    for (int n = 0; n < N_BAS; n++) w[n] = g_wT[n * M_TOT + m];

#pragma unroll
    for (int s = 0; s < 30; s++) {
        const float4* cf = (const float4*)&sc[s * N_BAS];
        float a0 = 0.f, a1 = 0.f, a2 = 0.f, a3 = 0.f;
#pragma unroll
        for (int i = 0; i < 8; i++) {
            float4 f = cf[i];
            a0 = fmaf(w[4 * i + 0], f.x, a0);
            a1 = fmaf(w[4 * i + 1], f.y, a1);
            a2 = fmaf(w[4 * i + 2], f.z, a2);
            a3 = fmaf(w[4 * i + 3], f.w, a3);
        }
        g_F[(t0 + s) * M_TOT + m] = (a0 + a1) + (a2 + a3);
    }
}

// ---------------------------------------------------------------------------
// rollout: sequential Euler per channel; streaming, memory-bound.
__global__ __launch_bounds__(128)
void rollout_kernel(float* __restrict__ outA, float* __restrict__ outV) {
    __shared__ float tile[4][32 * 31];

    const int tid = threadIdx.x;
    const int lane = tid & 31;
    const int warp = tid >> 5;
    const int m = blockIdx.x * 128 + tid;
    const int m0 = m - lane;
    float* wt = tile[warp];

    const float4 p = g_par[m];
    const float goal = p.x, az = p.y, vv = p.w;
    float y = p.z;
    float z = 0.01f;
    const float bz = az * 0.25f;

    for (int ch = 0; ch < 10; ch++) {
        float f[30];
#pragma unroll
        for (int s = 0; s < 30; s++)
            f[s] = g_F[(size_t)(ch * 30 + s) * M_TOT + m];

#pragma unroll
        for (int s = 0; s < 30; s++) {
            wt[lane * 31 + s] = z * DT_F;            // a[t] = z_t * DT
            const float dz = fmaf(az, fmaf(bz, goal - y, -z), f[s]);
            y = fmaf(z, DT_F, y);
            z = fmaf(dz, DT_F, z);
        }
        __syncwarp();
#pragma unroll
        for (int r = 0; r < 32; r++) {
            const float vr = __shfl_sync(0xffffffffu, vv, r);
            if (lane < 30) {
                const size_t base = (size_t)(m0 + r) * 300 + ch * 30 + lane;
                outA[base] = wt[r * 31 + lane];
                outV[base] = vr;
            }
        }
        __syncwarp();
    }
}

// ---------------------------------------------------------------------------
extern "C" void kernel_launch(void* const* d_in, const int* in_sizes, int n_in,
                              void* d_out, int out_size) {
    const float* state  = (const float*)d_in[0];
    const float* fc1_w  = (const float*)d_in[1];
    const float* fc1_b  = (const float*)d_in[2];
    const float* fc2m_w = (const float*)d_in[3];
    const float* fc2m_b = (const float*)d_in[4];
    const float* sig_w  = (const float*)d_in[5];
    const float* sig_b  = (const float*)d_in[6];
    const float* val_w  = (const float*)d_in[7];
    const float* val_b  = (const float*)d_in[8];
    const float* dmp_c  = (const float*)d_in[9];
    const float* dmp_s2 = (const float*)d_in[10];

    float* out = (float*)d_out;
    float* outA = out;                               // [B,2,300]
    float* outS = out + (size_t)M_TOT * T_STEPS;     // [B,2,1]
    float* outV = outS + M_TOT;                      // [B,2,300]

    coef_kernel<<<1, 320>>>(dmp_c, dmp_s2);
    params_kernel<<<M_TOT / 128, 128>>>(state, fc1_w, fc1_b, fc2m_w, fc2m_b,
                                        sig_w, sig_b, val_w, val_b, outS);
    dim3 ggrid(M_TOT / 128, T_STEPS / 30);
    gemm_kernel<<<ggrid, 128>>>();
    rollout_kernel<<<M_TOT / 128, 128>>>(outA, outV);
}